// round 15
// baseline (speedup 1.0000x reference)
#include <cuda_runtime.h>
#include <cuda_fp16.h>
#include <cstdint>

#define BB 4
#define TT 2048
#define DD 512
#define HH 8
#define DKK 64

// fp16 scratch. q/k/x: [b,h,t,dk].  v: TRANSPOSED [b,h,dk,t].
__device__ __half g_qh[BB*HH*TT*DKK];
__device__ __half g_kh[BB*HH*TT*DKK];
__device__ __half g_vh[BB*HH*TT*DKK];
__device__ __half g_xh[BB*HH*TT*DKK];
// fp16 copies of inputs/weights
__device__ __half g_qi[BB*TT*DD];
__device__ __half g_ki[BB*TT*DD];
__device__ __half g_vi[BB*TT*DD];
__device__ __half g_wq[DD*DD];
__device__ __half g_wk[DD*DD];
__device__ __half g_wv[DD*DD];
__device__ __half g_wo[DD*DD];

__device__ __forceinline__ void mma16(float* d, const uint32_t* a, const uint32_t* b){
    asm volatile(
      "mma.sync.aligned.m16n8k16.row.col.f32.f16.f16.f32 "
      "{%0,%1,%2,%3}, {%4,%5,%6,%7}, {%8,%9}, {%0,%1,%2,%3};"
      : "+f"(d[0]),"+f"(d[1]),"+f"(d[2]),"+f"(d[3])
      : "r"(a[0]),"r"(a[1]),"r"(a[2]),"r"(a[3]), "r"(b[0]),"r"(b[1]));
}
__device__ __forceinline__ void ldsm4(uint32_t& r0, uint32_t& r1,
                                      uint32_t& r2, uint32_t& r3, uint32_t a){
    asm volatile("ldmatrix.sync.aligned.m8n8.x4.shared.b16 {%0,%1,%2,%3}, [%4];"
        : "=r"(r0),"=r"(r1),"=r"(r2),"=r"(r3) : "r"(a));
}
__device__ __forceinline__ uint2 f4h(float4 v){
    __half2 lo = __floats2half2_rn(v.x, v.y);
    __half2 hi = __floats2half2_rn(v.z, v.w);
    return make_uint2(*(uint32_t*)&lo, *(uint32_t*)&hi);
}
__device__ __forceinline__ uint32_t smem_u32(const void* p){
    uint32_t a;
    asm("{ .reg .u64 t; cvta.to.shared.u64 t, %1; cvt.u32.u64 %0, t; }"
        : "=r"(a) : "l"(p));
    return a;
}
__device__ __forceinline__ void cp16(uint32_t s, const void* g){
    asm volatile("cp.async.cg.shared.global [%0], [%1], 16;" :: "r"(s), "l"(g) : "memory");
}
__device__ __forceinline__ void cpcommit(){
    asm volatile("cp.async.commit_group;" ::: "memory");
}
template<int N> __device__ __forceinline__ void cpwait(){
    asm volatile("cp.async.wait_group %0;" :: "n"(N) : "memory");
}
__device__ __forceinline__ uint32_t ex2h2(uint32_t x){
    uint32_t r;
    asm("ex2.approx.f16x2 %0, %1;" : "=r"(r) : "r"(x));
    return r;
}
__device__ __forceinline__ float rcpf(float x){
    float r;
    asm("rcp.approx.ftz.f32 %0, %1;" : "=f"(r) : "f"(x));
    return r;
}
// streaming store: evict-first in L2 (sigmoid output is never re-read)
__device__ __forceinline__ void stg_cs_f2(float* p, float x, float y){
    asm volatile("st.global.cs.v2.f32 [%0], {%1,%2};"
        :: "l"(p), "f"(x), "f"(y) : "memory");
}

// =============================================================
// Convert fp32 inputs + weights to fp16 scratch (4 float4/thread)
// =============================================================
#define IN4 1048576
#define W4  65536
__global__ __launch_bounds__(256) void cvt_kernel(
    const float* __restrict__ q, const float* __restrict__ k,
    const float* __restrict__ v,
    const float* __restrict__ Wq, const float* __restrict__ Wk,
    const float* __restrict__ Wv, const float* __restrict__ Wo)
{
    int i0 = (blockIdx.x * 256 + threadIdx.x) * 4;
    const float* s; __half* d; int off;
    if (i0 < 3*IN4) {
        int w = i0 / IN4; off = i0 - w*IN4;
        s = w==0 ? q : (w==1 ? k : v);
        d = w==0 ? g_qi : (w==1 ? g_ki : g_vi);
    } else {
        int j = i0 - 3*IN4;
        int w = j / W4; off = j - w*W4;
        s = w==0 ? Wq : (w==1 ? Wk : (w==2 ? Wv : Wo));
        d = w==0 ? g_wq : (w==1 ? g_wk : (w==2 ? g_wv : g_wo));
    }
    #pragma unroll
    for (int j = 0; j < 4; j++) {
        float4 vv = __ldg((const float4*)s + off + j);
        *(uint2*)(d + (size_t)(off + j)*4) = f4h(vv);
    }
}

// =============================================================
// QKV projection, fp16 + cp.async 3-stage + ldmatrix.
// smem: stage s @ s*36864 (A 18432 + B 18432), bias @110592
// =============================================================
#define PJ_SMEM 111104

__global__ __launch_bounds__(256, 2) void qkv_mma_kernel(
    const float* __restrict__ bq, const float* __restrict__ bk,
    const float* __restrict__ bv)
{
    extern __shared__ char smn[];
    const int which = blockIdx.z;
    const __half* A  = which == 0 ? g_qi : (which == 1 ? g_ki : g_vi);
    const __half* W  = which == 0 ? g_wq : (which == 1 ? g_wk : g_wv);
    const float* bias= which == 0 ? bq   : (which == 1 ? bk   : bv);
    __half* outp     = which == 0 ? g_qh : (which == 1 ? g_kh : g_vh);

    float* sBias = (float*)(smn + 110592);
    const uint32_t sb = smem_u32(smn);

    const int tid = threadIdx.x;
    const int lane = tid & 31, wid = tid >> 5;
    const int wm = wid & 1, wn = wid >> 1;
    const int m0 = blockIdx.y * 128, n0 = blockIdx.x * 128;

    if (tid < 32)
        *(float4*)&sBias[tid*4] = *(const float4*)(bias + n0 + tid*4);

    const int lrow = tid >> 3, lc8 = (tid & 7) * 8;
    const uint32_t aoff = (uint32_t)(((lane & 15) * 72 + ((lane >> 4) << 3)) * 2);
    const uint32_t boff = (uint32_t)((((lane & 7) + ((lane >> 4) << 3)) * 72 + (lane & 8)) * 2);

    auto issue = [&](int cc, int s){
        #pragma unroll
        for (int i = 0; i < 4; i++) {
            int row = lrow + i * 32;
            uint32_t so = sb + s*36864 + row*144 + lc8*2;
            cp16(so, A + (size_t)(m0+row)*512 + cc*64 + lc8);
            cp16(so + 18432, W + (size_t)(n0+row)*512 + cc*64 + lc8);
        }
        cpcommit();
    };

    issue(0, 0);
    issue(1, 1);
    issue(2, 2);

    float acc[4][4][4] = {};

    for (int c = 0; c < 8; c++) {
        if (c < 6) cpwait<2>();
        else if (c == 6) cpwait<1>();
        else cpwait<0>();
        __syncthreads();
        const uint32_t sbA = sb + (c % 3) * 36864;
        const uint32_t sbB = sbA + 18432;
        #pragma unroll
        for (int ks = 0; ks < 4; ks++) {
            uint32_t af[4][4], bf[4][2];
            #pragma unroll
            for (int mt = 0; mt < 4; mt++)
                ldsm4(af[mt][0], af[mt][1], af[mt][2], af[mt][3],
                      sbA + (wm*64 + mt*16)*144 + ks*32 + aoff);
            ldsm4(bf[0][0], bf[0][1], bf[1][0], bf[1][1],
                  sbB + (wn*32)*144 + ks*32 + boff);
            ldsm4(bf[2][0], bf[2][1], bf[3][0], bf[3][1],
                  sbB + (wn*32 + 16)*144 + ks*32 + boff);
            #pragma unroll
            for (int mt = 0; mt < 4; mt++)
                #pragma unroll
                for (int nt = 0; nt < 4; nt++)
                    mma16(acc[mt][nt], af[mt], bf[nt]);
        }
        __syncthreads();
        if (c + 3 < 8) issue(c + 3, c % 3);
    }

    #pragma unroll
    for (int mt = 0; mt < 4; mt++) {
        const int m = m0 + wm*64 + mt*16 + (lane>>2);
        const int b0_ = m >> 11, t0_ = m & 2047;
        const int b1_ = (m+8) >> 11, t1_ = (m+8) & 2047;
        #pragma unroll
        for (int nt = 0; nt < 4; nt++) {
            const int nl = wn*32 + nt*8 + (lane&3)*2;
            const int n = n0 + nl;
            const int h_ = n >> 6, dk_ = n & 63;
            float bx = sBias[nl], by = sBias[nl+1];
            float v0 = acc[mt][nt][0] + bx, v1 = acc[mt][nt][1] + by;
            float v2 = acc[mt][nt][2] + bx, v3 = acc[mt][nt][3] + by;
            if (which == 2) {
                __half* base = outp + ((size_t)(b0_*HH + h_)*DKK + dk_)*TT;
                base[t0_]       = __float2half_rn(v0);
                base[TT + t0_]  = __float2half_rn(v1);
                __half* base1 = outp + ((size_t)(b1_*HH + h_)*DKK + dk_)*TT;
                base1[t1_]      = __float2half_rn(v2);
                base1[TT + t1_] = __float2half_rn(v3);
            } else {
                *(__half2*)(outp + (((size_t)b0_*HH + h_)*TT + t0_)*DKK + dk_) =
                    __floats2half2_rn(v0, v1);
                *(__half2*)(outp + (((size_t)b1_*HH + h_)*TT + t1_)*DKK + dk_) =
                    __floats2half2_rn(v2, v3);
            }
        }
    }
}

// =============================================================
// Output projection: A = g_xh (head-split fp16), B = g_wo fp16
// =============================================================
__global__ __launch_bounds__(256, 2) void oproj_mma_kernel(
    const float* __restrict__ bo, float* __restrict__ outp)
{
    extern __shared__ char smn[];
    float* sBias = (float*)(smn + 110592);
    const uint32_t sb = smem_u32(smn);

    const int tid = threadIdx.x;
    const int lane = tid & 31, wid = tid >> 5;
    const int wm = wid & 1, wn = wid >> 1;
    const int m0 = blockIdx.y * 128, n0 = blockIdx.x * 128;

    if (tid < 32)
        *(float4*)&sBias[tid*4] = *(const float4*)(bo + n0 + tid*4);

    const int lrow = tid >> 3, lc8 = (tid & 7) * 8;
    const uint32_t aoff = (uint32_t)(((lane & 15) * 72 + ((lane >> 4) << 3)) * 2);
    const uint32_t boff = (uint32_t)((((lane & 7) + ((lane >> 4) << 3)) * 72 + (lane & 8)) * 2);

    auto issue = [&](int cc, int s){
        #pragma unroll
        for (int i = 0; i < 4; i++) {
            int row = lrow + i * 32;
            const int m = m0 + row;
            const int b_ = m >> 11, t_ = m & 2047;
            uint32_t so = sb + s*36864 + row*144 + lc8*2;
            cp16(so, g_xh + (((size_t)b_*HH + cc)*TT + t_)*DKK + lc8);
            cp16(so + 18432, g_wo + (size_t)(n0+row)*512 + cc*64 + lc8);
        }
        cpcommit();
    };

    issue(0, 0);
    issue(1, 1);
    issue(2, 2);

    float acc[4][4][4] = {};

    for (int c = 0; c < 8; c++) {
        if (c < 6) cpwait<2>();
        else if (c == 6) cpwait<1>();
        else cpwait<0>();
        __syncthreads();
        const uint32_t sbA = sb + (c % 3) * 36864;
        const uint32_t sbB = sbA + 18432;
        #pragma unroll
        for (int ks = 0; ks < 4; ks++) {
            uint32_t af[4][4], bf[4][2];
            #pragma unroll
            for (int mt = 0; mt < 4; mt++)
                ldsm4(af[mt][0], af[mt][1], af[mt][2], af[mt][3],
                      sbA + (wm*64 + mt*16)*144 + ks*32 + aoff);
            ldsm4(bf[0][0], bf[0][1], bf[1][0], bf[1][1],
                  sbB + (wn*32)*144 + ks*32 + boff);
            ldsm4(bf[2][0], bf[2][1], bf[3][0], bf[3][1],
                  sbB + (wn*32 + 16)*144 + ks*32 + boff);
            #pragma unroll
            for (int mt = 0; mt < 4; mt++)
                #pragma unroll
                for (int nt = 0; nt < 4; nt++)
                    mma16(acc[mt][nt], af[mt], bf[nt]);
        }
        __syncthreads();
        if (c + 3 < 8) issue(c + 3, c % 3);
    }

    #pragma unroll
    for (int mt = 0; mt < 4; mt++) {
        const int m = m0 + wm*64 + mt*16 + (lane>>2);
        #pragma unroll
        for (int nt = 0; nt < 4; nt++) {
            const int nl = wn*32 + nt*8 + (lane&3)*2;
            float bx = sBias[nl], by = sBias[nl+1];
            *(float2*)(outp + (size_t)m*512 + n0 + nl) =
                make_float2(acc[mt][nt][0] + bx, acc[mt][nt][1] + by);
            *(float2*)(outp + (size_t)(m+8)*512 + n0 + nl) =
                make_float2(acc[mt][nt][2] + bx, acc[mt][nt][3] + by);
        }
    }
}

// =============================================================
// Fused attention, FA2-style, quarter-split, 3 CTAs/SM (reg cap 84).
// smem: sQ@0 (18432), sK ring @18432 (2x18432), sVt@55296 (17408)
// =============================================================
#define SQ_O 0
#define SK_O 18432
#define SVT_O 55296
#define ATT_SMEM 72704

__global__ __launch_bounds__(256, 3) void attn_mma_kernel(
    const int* __restrict__ mask, float* __restrict__ sig)
{
    extern __shared__ char smn[];
    const uint32_t sb = smem_u32(smn);

    const int tid = threadIdx.x;
    const int lane = tid & 31, wid = tid >> 5;
    const int wrow = wid * 16;                 // warp's q rows [wrow, wrow+16)
    const int bh = blockIdx.y;
    const int b_ = bh >> 3;
    const int q0 = blockIdx.x * 128;

    const __half* Qg = g_qh + (size_t)bh * TT * DKK;
    const __half* Kg = g_kh + (size_t)bh * TT * DKK;
    const __half* Vg = g_vh + (size_t)bh * DKK * TT;   // [dk][t]
    float* sigbh = sig + (size_t)bh * TT * TT;
    const int* maskb = mask + b_ * TT;

    const int krow = tid >> 3, kc8 = (tid & 7) * 8;
    const int vdk = tid >> 4, vc8 = (tid & 15) * 8;

    const uint32_t aoff  = (uint32_t)(((lane & 15) * 72 + ((lane >> 4) << 3)) * 2);
    const uint32_t boff  = (uint32_t)((((lane & 7) + ((lane >> 4) << 3)) * 72 + (lane & 8)) * 2);
    const uint32_t boffV = (uint32_t)((((lane & 7) + ((lane >> 4) << 3)) * 136 + (lane & 8)) * 2);

    // group 0: Q ; group 1: K(0)
    #pragma unroll
    for (int i = 0; i < 4; i++) {
        int row = krow + i * 32;
        cp16(sb + SQ_O + row*144 + kc8*2, Qg + (size_t)(q0+row)*DKK + kc8);
    }
    cpcommit();
    #pragma unroll
    for (int i = 0; i < 4; i++) {
        int row = krow + i * 32;
        cp16(sb + SK_O + row*144 + kc8*2, Kg + (size_t)row*DKK + kc8);
    }
    cpcommit();

    float o[8][4] = {};
    float lsum0 = 0.0f, lsum1 = 0.0f;
    uint32_t qf[4][4];
    const float SC = 0.180336880f;   // 0.125 * log2(e)
    const int rg0 = q0 + wrow + (lane >> 2);

    for (int t = 0; t < 16; t++) {
        const int kv0 = t * 128;
        __syncthreads();   // PV(t-1) done reading sVt

        // group: V(t)
        #pragma unroll
        for (int i = 0; i < 4; i++) {
            int dk = vdk + i * 16;
            cp16(sb + SVT_O + dk*272 + vc8*2, Vg + (size_t)dk*TT + kv0 + vc8);
        }
        cpcommit();
        // group: K(t+1)
        if (t < 15) {
            const uint32_t kb = sb + SK_O + ((t+1) & 1) * 18432;
            #pragma unroll
            for (int i = 0; i < 4; i++) {
                int row = krow + i * 32;
                cp16(kb + row*144 + kc8*2, Kg + (size_t)(kv0+128+row)*DKK + kc8);
            }
            cpcommit();
            cpwait<2>();   // K(t) (and Q at t=0) arrived
        } else {
            cpwait<1>();
        }
        __syncthreads();

        if (t == 0) {      // hoist Q fragments into registers, once
            #pragma unroll
            for (int ks = 0; ks < 4; ks++)
                ldsm4(qf[ks][0], qf[ks][1], qf[ks][2], qf[ks][3],
                      sb + SQ_O + wrow*144 + ks*32 + aoff);
        }

        const uint32_t sbK = sb + SK_O + (t & 1) * 18432;

        #pragma unroll
        for (int qn = 0; qn < 4; qn++) {
            // ---- S(quarter) = Q @ K^T : m16 x n32 x k64 ----
            float s[4][4] = {};
            #pragma unroll
            for (int ks = 0; ks < 4; ks++) {
                uint32_t b0,b1,b2,b3, c0,c1,c2,c3;
                ldsm4(b0,b1,b2,b3, sbK + (qn*32)*144      + ks*32 + boff);
                ldsm4(c0,c1,c2,c3, sbK + (qn*32 + 16)*144 + ks*32 + boff);
                uint32_t bf0[2]={b0,b1}, bf1[2]={b2,b3};
                uint32_t bf2[2]={c0,c1}, bf3[2]={c2,c3};
                mma16(s[0], qf[ks], bf0);
                mma16(s[1], qf[ks], bf1);
                mma16(s[2], qf[ks], bf2);
                mma16(s[3], qf[ks], bf3);
            }
            // ---- epilogue: sigmoid -> gmem (.cs), P -> regs ----
            uint32_t pf[2][4];
            #pragma unroll
            for (int nt = 0; nt < 4; nt++) {
                const int cl = qn*32 + nt*8 + (lane & 3)*2;
                int2 mm = __ldg((const int2*)(maskb + kv0 + cl));
                const float m0_ = mm.x ? 0.0f : -1e9f;
                const float m1_ = mm.y ? 0.0f : -1e9f;
                float s0 = fmaf(s[nt][0], SC, m0_);
                float s1 = fmaf(s[nt][1], SC, m1_);
                float s2 = fmaf(s[nt][2], SC, m0_);
                float s3 = fmaf(s[nt][3], SC, m1_);
                __half2 h01 = __floats2half2_rn(s0, s1);
                __half2 h23 = __floats2half2_rn(s2, s3);
                uint32_t p01 = ex2h2(*(uint32_t*)&h01);
                uint32_t p23 = ex2h2(*(uint32_t*)&h23);
                float2 f01 = __half22float2(*(__half2*)&p01);
                float2 f23 = __half22float2(*(__half2*)&p23);
                // 4-way batched reciprocal: one MUFU.RCP for 4 sigmoids
                float d0 = 1.0f + f01.x, d1 = 1.0f + f01.y;
                float d2 = 1.0f + f23.x, d3 = 1.0f + f23.y;
                float d01 = d0 * d1, d23 = d2 * d3;
                float r = rcpf(d01 * d23);
                float r01 = r * d23, r23 = r * d01;
                stg_cs_f2(sigbh + (size_t)rg0*TT + kv0 + cl,
                          f01.x * d1 * r01, f01.y * d0 * r01);
                stg_cs_f2(sigbh + (size_t)(rg0+8)*TT + kv0 + cl,
                          f23.x * d3 * r23, f23.y * d2 * r23);
                lsum0 += f01.x + f01.y;
                lsum1 += f23.x + f23.y;
                pf[nt>>1][(nt&1)*2]   = p01;
                pf[nt>>1][(nt&1)*2+1] = p23;
            }
            if (qn == 0) {                 // V(t) needed from here on
                if (t < 15) cpwait<1>(); else cpwait<0>();
                __syncthreads();
            }
            // ---- O += P(quarter) @ V : m16 x n64 x k32 ----
            #pragma unroll
            for (int c = 0; c < 2; c++) {
                const uint32_t colb = (uint32_t)(qn*2 + c) * 32;
                #pragma unroll
                for (int bb = 0; bb < 4; bb++) {
                    uint32_t b0,b1,b2,b3;
                    ldsm4(b0,b1,b2,b3, sb + SVT_O + (bb*16)*272 + colb + boffV);
                    uint32_t bf0[2] = {b0,b1}, bf1[2] = {b2,b3};
                    mma16(o[bb*2],   pf[c], bf0);
                    mma16(o[bb*2+1], pf[c], bf1);
                }
            }
        }
    }

    // row sums: reduce across the 4 lanes sharing each row
    lsum0 += __shfl_xor_sync(0xffffffffu, lsum0, 1);
    lsum0 += __shfl_xor_sync(0xffffffffu, lsum0, 2);
    lsum1 += __shfl_xor_sync(0xffffffffu, lsum1, 1);
    lsum1 += __shfl_xor_sync(0xffffffffu, lsum1, 2);
    const float li0 = 1.0f / lsum0;
    const float li1 = 1.0f / lsum1;

    #pragma unroll
    for (int nt = 0; nt < 8; nt++) {
        const int cc = nt*8 + (lane & 3)*2;
        *(__half2*)(g_xh + ((size_t)bh*TT + rg0)*DKK + cc) =
            __floats2half2_rn(o[nt][0]*li0, o[nt][1]*li0);
        *(__half2*)(g_xh + ((size_t)bh*TT + rg0 + 8)*DKK + cc) =
            __floats2half2_rn(o[nt][2]*li1, o[nt][3]*li1);
    }
}

// -------------------------------------------------------------
extern "C" void kernel_launch(void* const* d_in, const int* in_sizes, int n_in,
                              void* d_out, int out_size)
{
    const float* query = (const float*)d_in[0];
    const float* key   = (const float*)d_in[1];
    const float* value = (const float*)d_in[2];
    const int*   mask  = (const int*)d_in[3];
    const float* Wq = (const float*)d_in[4];
    const float* bq = (const float*)d_in[5];
    const float* Wk = (const float*)d_in[6];
    const float* bk = (const float*)d_in[7];
    const float* Wv = (const float*)d_in[8];
    const float* bv = (const float*)d_in[9];
    const float* Wo = (const float*)d_in[10];
    const float* bo = (const float*)d_in[11];

    float* out0 = (float*)d_out;                 // (B,T,D)
    float* sig  = out0 + (size_t)BB * TT * DD;   // (B,H,T,T)

    static bool configured = false;
    if (!configured) {
        cudaFuncSetAttribute(attn_mma_kernel,
            cudaFuncAttributeMaxDynamicSharedMemorySize, ATT_SMEM);
        cudaFuncSetAttribute(qkv_mma_kernel,
            cudaFuncAttributeMaxDynamicSharedMemorySize, PJ_SMEM);
        cudaFuncSetAttribute(oproj_mma_kernel,
            cudaFuncAttributeMaxDynamicSharedMemorySize, PJ_SMEM);
        configured = true;
    }

    cvt_kernel<<<3328, 256>>>(query, key, value, Wq, Wk, Wv, Wo);
    qkv_mma_kernel<<<dim3(4, 64, 3), 256, PJ_SMEM>>>(bq, bk, bv);
    attn_mma_kernel<<<dim3(16, 32), 256, ATT_SMEM>>>(mask, sig);
    oproj_mma_kernel<<<dim3(4, 64), 256, PJ_SMEM>>>(bo, out0);
}

// round 16
// speedup vs baseline: 1.4434x; 1.4434x over previous
#include <cuda_runtime.h>
#include <cuda_fp16.h>
#include <cstdint>

#define BB 4
#define TT 2048
#define DD 512
#define HH 8
#define DKK 64

// fp16 scratch. q/k/x: [b,h,t,dk].  v: TRANSPOSED [b,h,dk,t].
__device__ __half g_qh[BB*HH*TT*DKK];
__device__ __half g_kh[BB*HH*TT*DKK];
__device__ __half g_vh[BB*HH*TT*DKK];
__device__ __half g_xh[BB*HH*TT*DKK];
// fp16 copies of inputs/weights
__device__ __half g_qi[BB*TT*DD];
__device__ __half g_ki[BB*TT*DD];
__device__ __half g_vi[BB*TT*DD];
__device__ __half g_wq[DD*DD];
__device__ __half g_wk[DD*DD];
__device__ __half g_wv[DD*DD];
__device__ __half g_wo[DD*DD];

__device__ __forceinline__ void mma16(float* d, const uint32_t* a, const uint32_t* b){
    asm volatile(
      "mma.sync.aligned.m16n8k16.row.col.f32.f16.f16.f32 "
      "{%0,%1,%2,%3}, {%4,%5,%6,%7}, {%8,%9}, {%0,%1,%2,%3};"
      : "+f"(d[0]),"+f"(d[1]),"+f"(d[2]),"+f"(d[3])
      : "r"(a[0]),"r"(a[1]),"r"(a[2]),"r"(a[3]), "r"(b[0]),"r"(b[1]));
}
__device__ __forceinline__ void ldsm4(uint32_t& r0, uint32_t& r1,
                                      uint32_t& r2, uint32_t& r3, uint32_t a){
    asm volatile("ldmatrix.sync.aligned.m8n8.x4.shared.b16 {%0,%1,%2,%3}, [%4];"
        : "=r"(r0),"=r"(r1),"=r"(r2),"=r"(r3) : "r"(a));
}
__device__ __forceinline__ uint2 f4h(float4 v){
    __half2 lo = __floats2half2_rn(v.x, v.y);
    __half2 hi = __floats2half2_rn(v.z, v.w);
    return make_uint2(*(uint32_t*)&lo, *(uint32_t*)&hi);
}
__device__ __forceinline__ uint32_t smem_u32(const void* p){
    uint32_t a;
    asm("{ .reg .u64 t; cvta.to.shared.u64 t, %1; cvt.u32.u64 %0, t; }"
        : "=r"(a) : "l"(p));
    return a;
}
__device__ __forceinline__ void cp16(uint32_t s, const void* g){
    asm volatile("cp.async.cg.shared.global [%0], [%1], 16;" :: "r"(s), "l"(g) : "memory");
}
__device__ __forceinline__ void cpcommit(){
    asm volatile("cp.async.commit_group;" ::: "memory");
}
template<int N> __device__ __forceinline__ void cpwait(){
    asm volatile("cp.async.wait_group %0;" :: "n"(N) : "memory");
}
__device__ __forceinline__ uint32_t ex2h2(uint32_t x){
    uint32_t r;
    asm("ex2.approx.f16x2 %0, %1;" : "=r"(r) : "r"(x));
    return r;
}
__device__ __forceinline__ float rcpf(float x){
    float r;
    asm("rcp.approx.ftz.f32 %0, %1;" : "=f"(r) : "f"(x));
    return r;
}
// streaming store: evict-first in L2 (sigmoid output is never re-read)
__device__ __forceinline__ void stg_cs_f2(float* p, float x, float y){
    asm volatile("st.global.cs.v2.f32 [%0], {%1,%2};"
        :: "l"(p), "f"(x), "f"(y) : "memory");
}

// =============================================================
// Convert fp32 inputs + weights to fp16 scratch (4 float4/thread)
// =============================================================
#define IN4 1048576
#define W4  65536
__global__ __launch_bounds__(256) void cvt_kernel(
    const float* __restrict__ q, const float* __restrict__ k,
    const float* __restrict__ v,
    const float* __restrict__ Wq, const float* __restrict__ Wk,
    const float* __restrict__ Wv, const float* __restrict__ Wo)
{
    int i0 = (blockIdx.x * 256 + threadIdx.x) * 4;
    const float* s; __half* d; int off;
    if (i0 < 3*IN4) {
        int w = i0 / IN4; off = i0 - w*IN4;
        s = w==0 ? q : (w==1 ? k : v);
        d = w==0 ? g_qi : (w==1 ? g_ki : g_vi);
    } else {
        int j = i0 - 3*IN4;
        int w = j / W4; off = j - w*W4;
        s = w==0 ? Wq : (w==1 ? Wk : (w==2 ? Wv : Wo));
        d = w==0 ? g_wq : (w==1 ? g_wk : (w==2 ? g_wv : g_wo));
    }
    #pragma unroll
    for (int j = 0; j < 4; j++) {
        float4 vv = __ldg((const float4*)s + off + j);
        *(uint2*)(d + (size_t)(off + j)*4) = f4h(vv);
    }
}

// =============================================================
// QKV projection, fp16 + cp.async 3-stage + ldmatrix.
// smem: stage s @ s*36864 (A 18432 + B 18432), bias @110592
// =============================================================
#define PJ_SMEM 111104

__global__ __launch_bounds__(256, 2) void qkv_mma_kernel(
    const float* __restrict__ bq, const float* __restrict__ bk,
    const float* __restrict__ bv)
{
    extern __shared__ char smn[];
    const int which = blockIdx.z;
    const __half* A  = which == 0 ? g_qi : (which == 1 ? g_ki : g_vi);
    const __half* W  = which == 0 ? g_wq : (which == 1 ? g_wk : g_wv);
    const float* bias= which == 0 ? bq   : (which == 1 ? bk   : bv);
    __half* outp     = which == 0 ? g_qh : (which == 1 ? g_kh : g_vh);

    float* sBias = (float*)(smn + 110592);
    const uint32_t sb = smem_u32(smn);

    const int tid = threadIdx.x;
    const int lane = tid & 31, wid = tid >> 5;
    const int wm = wid & 1, wn = wid >> 1;
    const int m0 = blockIdx.y * 128, n0 = blockIdx.x * 128;

    if (tid < 32)
        *(float4*)&sBias[tid*4] = *(const float4*)(bias + n0 + tid*4);

    const int lrow = tid >> 3, lc8 = (tid & 7) * 8;
    const uint32_t aoff = (uint32_t)(((lane & 15) * 72 + ((lane >> 4) << 3)) * 2);
    const uint32_t boff = (uint32_t)((((lane & 7) + ((lane >> 4) << 3)) * 72 + (lane & 8)) * 2);

    auto issue = [&](int cc, int s){
        #pragma unroll
        for (int i = 0; i < 4; i++) {
            int row = lrow + i * 32;
            uint32_t so = sb + s*36864 + row*144 + lc8*2;
            cp16(so, A + (size_t)(m0+row)*512 + cc*64 + lc8);
            cp16(so + 18432, W + (size_t)(n0+row)*512 + cc*64 + lc8);
        }
        cpcommit();
    };

    issue(0, 0);
    issue(1, 1);
    issue(2, 2);

    float acc[4][4][4] = {};

    for (int c = 0; c < 8; c++) {
        if (c < 6) cpwait<2>();
        else if (c == 6) cpwait<1>();
        else cpwait<0>();
        __syncthreads();
        const uint32_t sbA = sb + (c % 3) * 36864;
        const uint32_t sbB = sbA + 18432;
        #pragma unroll
        for (int ks = 0; ks < 4; ks++) {
            uint32_t af[4][4], bf[4][2];
            #pragma unroll
            for (int mt = 0; mt < 4; mt++)
                ldsm4(af[mt][0], af[mt][1], af[mt][2], af[mt][3],
                      sbA + (wm*64 + mt*16)*144 + ks*32 + aoff);
            ldsm4(bf[0][0], bf[0][1], bf[1][0], bf[1][1],
                  sbB + (wn*32)*144 + ks*32 + boff);
            ldsm4(bf[2][0], bf[2][1], bf[3][0], bf[3][1],
                  sbB + (wn*32 + 16)*144 + ks*32 + boff);
            #pragma unroll
            for (int mt = 0; mt < 4; mt++)
                #pragma unroll
                for (int nt = 0; nt < 4; nt++)
                    mma16(acc[mt][nt], af[mt], bf[nt]);
        }
        __syncthreads();
        if (c + 3 < 8) issue(c + 3, c % 3);
    }

    #pragma unroll
    for (int mt = 0; mt < 4; mt++) {
        const int m = m0 + wm*64 + mt*16 + (lane>>2);
        const int b0_ = m >> 11, t0_ = m & 2047;
        const int b1_ = (m+8) >> 11, t1_ = (m+8) & 2047;
        #pragma unroll
        for (int nt = 0; nt < 4; nt++) {
            const int nl = wn*32 + nt*8 + (lane&3)*2;
            const int n = n0 + nl;
            const int h_ = n >> 6, dk_ = n & 63;
            float bx = sBias[nl], by = sBias[nl+1];
            float v0 = acc[mt][nt][0] + bx, v1 = acc[mt][nt][1] + by;
            float v2 = acc[mt][nt][2] + bx, v3 = acc[mt][nt][3] + by;
            if (which == 2) {
                __half* base = outp + ((size_t)(b0_*HH + h_)*DKK + dk_)*TT;
                base[t0_]       = __float2half_rn(v0);
                base[TT + t0_]  = __float2half_rn(v1);
                __half* base1 = outp + ((size_t)(b1_*HH + h_)*DKK + dk_)*TT;
                base1[t1_]      = __float2half_rn(v2);
                base1[TT + t1_] = __float2half_rn(v3);
            } else {
                *(__half2*)(outp + (((size_t)b0_*HH + h_)*TT + t0_)*DKK + dk_) =
                    __floats2half2_rn(v0, v1);
                *(__half2*)(outp + (((size_t)b1_*HH + h_)*TT + t1_)*DKK + dk_) =
                    __floats2half2_rn(v2, v3);
            }
        }
    }
}

// =============================================================
// Output projection: A = g_xh (head-split fp16), B = g_wo fp16
// =============================================================
__global__ __launch_bounds__(256, 2) void oproj_mma_kernel(
    const float* __restrict__ bo, float* __restrict__ outp)
{
    extern __shared__ char smn[];
    float* sBias = (float*)(smn + 110592);
    const uint32_t sb = smem_u32(smn);

    const int tid = threadIdx.x;
    const int lane = tid & 31, wid = tid >> 5;
    const int wm = wid & 1, wn = wid >> 1;
    const int m0 = blockIdx.y * 128, n0 = blockIdx.x * 128;

    if (tid < 32)
        *(float4*)&sBias[tid*4] = *(const float4*)(bo + n0 + tid*4);

    const int lrow = tid >> 3, lc8 = (tid & 7) * 8;
    const uint32_t aoff = (uint32_t)(((lane & 15) * 72 + ((lane >> 4) << 3)) * 2);
    const uint32_t boff = (uint32_t)((((lane & 7) + ((lane >> 4) << 3)) * 72 + (lane & 8)) * 2);

    auto issue = [&](int cc, int s){
        #pragma unroll
        for (int i = 0; i < 4; i++) {
            int row = lrow + i * 32;
            const int m = m0 + row;
            const int b_ = m >> 11, t_ = m & 2047;
            uint32_t so = sb + s*36864 + row*144 + lc8*2;
            cp16(so, g_xh + (((size_t)b_*HH + cc)*TT + t_)*DKK + lc8);
            cp16(so + 18432, g_wo + (size_t)(n0+row)*512 + cc*64 + lc8);
        }
        cpcommit();
    };

    issue(0, 0);
    issue(1, 1);
    issue(2, 2);

    float acc[4][4][4] = {};

    for (int c = 0; c < 8; c++) {
        if (c < 6) cpwait<2>();
        else if (c == 6) cpwait<1>();
        else cpwait<0>();
        __syncthreads();
        const uint32_t sbA = sb + (c % 3) * 36864;
        const uint32_t sbB = sbA + 18432;
        #pragma unroll
        for (int ks = 0; ks < 4; ks++) {
            uint32_t af[4][4], bf[4][2];
            #pragma unroll
            for (int mt = 0; mt < 4; mt++)
                ldsm4(af[mt][0], af[mt][1], af[mt][2], af[mt][3],
                      sbA + (wm*64 + mt*16)*144 + ks*32 + aoff);
            ldsm4(bf[0][0], bf[0][1], bf[1][0], bf[1][1],
                  sbB + (wn*32)*144 + ks*32 + boff);
            ldsm4(bf[2][0], bf[2][1], bf[3][0], bf[3][1],
                  sbB + (wn*32 + 16)*144 + ks*32 + boff);
            #pragma unroll
            for (int mt = 0; mt < 4; mt++)
                #pragma unroll
                for (int nt = 0; nt < 4; nt++)
                    mma16(acc[mt][nt], af[mt], bf[nt]);
        }
        __syncthreads();
        if (c + 3 < 8) issue(c + 3, c % 3);
    }

    #pragma unroll
    for (int mt = 0; mt < 4; mt++) {
        const int m = m0 + wm*64 + mt*16 + (lane>>2);
        #pragma unroll
        for (int nt = 0; nt < 4; nt++) {
            const int nl = wn*32 + nt*8 + (lane&3)*2;
            float bx = sBias[nl], by = sBias[nl+1];
            *(float2*)(outp + (size_t)m*512 + n0 + nl) =
                make_float2(acc[mt][nt][0] + bx, acc[mt][nt][1] + by);
            *(float2*)(outp + (size_t)(m+8)*512 + n0 + nl) =
                make_float2(acc[mt][nt][2] + bx, acc[mt][nt][3] + by);
        }
    }
}

// =============================================================
// Fused attention, FA2-style (R13 half-split body), 2 CTAs/SM.
// smem: sQ@0 (18432), sK ring @18432 (2x18432), sVt@55296 (17408)
// =============================================================
#define SQ_O 0
#define SK_O 18432
#define SVT_O 55296
#define ATT_SMEM 72704

__global__ __launch_bounds__(256, 2) void attn_mma_kernel(
    const int* __restrict__ mask, float* __restrict__ sig)
{
    extern __shared__ char smn[];
    const uint32_t sb = smem_u32(smn);

    const int tid = threadIdx.x;
    const int lane = tid & 31, wid = tid >> 5;
    const int wrow = wid * 16;                 // warp's q rows [wrow, wrow+16)
    const int bh = blockIdx.y;
    const int b_ = bh >> 3;
    const int q0 = blockIdx.x * 128;

    const __half* Qg = g_qh + (size_t)bh * TT * DKK;
    const __half* Kg = g_kh + (size_t)bh * TT * DKK;
    const __half* Vg = g_vh + (size_t)bh * DKK * TT;   // [dk][t]
    float* sigbh = sig + (size_t)bh * TT * TT;
    const int* maskb = mask + b_ * TT;

    const int krow = tid >> 3, kc8 = (tid & 7) * 8;
    const int vdk = tid >> 4, vc8 = (tid & 15) * 8;

    const uint32_t aoff  = (uint32_t)(((lane & 15) * 72 + ((lane >> 4) << 3)) * 2);
    const uint32_t boff  = (uint32_t)((((lane & 7) + ((lane >> 4) << 3)) * 72 + (lane & 8)) * 2);
    const uint32_t boffV = (uint32_t)((((lane & 7) + ((lane >> 4) << 3)) * 136 + (lane & 8)) * 2);

    // group 0: Q ; group 1: K(0)
    #pragma unroll
    for (int i = 0; i < 4; i++) {
        int row = krow + i * 32;
        cp16(sb + SQ_O + row*144 + kc8*2, Qg + (size_t)(q0+row)*DKK + kc8);
    }
    cpcommit();
    #pragma unroll
    for (int i = 0; i < 4; i++) {
        int row = krow + i * 32;
        cp16(sb + SK_O + row*144 + kc8*2, Kg + (size_t)row*DKK + kc8);
    }
    cpcommit();

    float o[8][4] = {};
    float lsum0 = 0.0f, lsum1 = 0.0f;
    uint32_t qf[4][4];
    const float SC = 0.180336880f;   // 0.125 * log2(e)
    const int rg0 = q0 + wrow + (lane >> 2);

    for (int t = 0; t < 16; t++) {
        const int kv0 = t * 128;
        __syncthreads();   // PV(t-1) done reading sVt

        // group: V(t)
        #pragma unroll
        for (int i = 0; i < 4; i++) {
            int dk = vdk + i * 16;
            cp16(sb + SVT_O + dk*272 + vc8*2, Vg + (size_t)dk*TT + kv0 + vc8);
        }
        cpcommit();
        // group: K(t+1)
        if (t < 15) {
            const uint32_t kb = sb + SK_O + ((t+1) & 1) * 18432;
            #pragma unroll
            for (int i = 0; i < 4; i++) {
                int row = krow + i * 32;
                cp16(kb + row*144 + kc8*2, Kg + (size_t)(kv0+128+row)*DKK + kc8);
            }
            cpcommit();
            cpwait<2>();   // K(t) (and Q at t=0) arrived
        } else {
            cpwait<1>();
        }
        __syncthreads();

        if (t == 0) {      // hoist Q fragments into registers, once
            #pragma unroll
            for (int ks = 0; ks < 4; ks++)
                ldsm4(qf[ks][0], qf[ks][1], qf[ks][2], qf[ks][3],
                      sb + SQ_O + wrow*144 + ks*32 + aoff);
        }

        const uint32_t sbK = sb + SK_O + (t & 1) * 18432;

        #pragma unroll
        for (int hn = 0; hn < 2; hn++) {
            // ---- S(half) = Q @ K^T : m16 x n64 x k64 ----
            float s[8][4] = {};
            #pragma unroll
            for (int ks = 0; ks < 4; ks++) {
                #pragma unroll
                for (int np = 0; np < 4; np++) {
                    uint32_t b0,b1,b2,b3;
                    ldsm4(b0,b1,b2,b3, sbK + (hn*64 + np*16)*144 + ks*32 + boff);
                    uint32_t bf0[2] = {b0,b1}, bf1[2] = {b2,b3};
                    mma16(s[np*2],   qf[ks], bf0);
                    mma16(s[np*2+1], qf[ks], bf1);
                }
            }
            // ---- epilogue: sigmoid -> gmem (.cs), P -> regs ----
            uint32_t pf[4][4];
            #pragma unroll
            for (int j = 0; j < 4; j++) {
                #pragma unroll
                for (int jj = 0; jj < 2; jj++) {
                    const int nt = j*2 + jj;
                    const int cl = hn*64 + nt*8 + (lane & 3)*2;
                    int2 mm = __ldg((const int2*)(maskb + kv0 + cl));
                    const float m0_ = mm.x ? 0.0f : -1e9f;
                    const float m1_ = mm.y ? 0.0f : -1e9f;
                    float s0 = fmaf(s[nt][0], SC, m0_);
                    float s1 = fmaf(s[nt][1], SC, m1_);
                    float s2 = fmaf(s[nt][2], SC, m0_);
                    float s3 = fmaf(s[nt][3], SC, m1_);
                    __half2 h01 = __floats2half2_rn(s0, s1);
                    __half2 h23 = __floats2half2_rn(s2, s3);
                    uint32_t p01 = ex2h2(*(uint32_t*)&h01);
                    uint32_t p23 = ex2h2(*(uint32_t*)&h23);
                    float2 f01 = __half22float2(*(__half2*)&p01);
                    float2 f23 = __half22float2(*(__half2*)&p23);
                    // 4-way batched reciprocal: one MUFU.RCP for 4 sigmoids
                    float d0 = 1.0f + f01.x, d1 = 1.0f + f01.y;
                    float d2 = 1.0f + f23.x, d3 = 1.0f + f23.y;
                    float d01 = d0 * d1, d23 = d2 * d3;
                    float r = rcpf(d01 * d23);
                    float r01 = r * d23, r23 = r * d01;
                    stg_cs_f2(sigbh + (size_t)rg0*TT + kv0 + cl,
                              f01.x * d1 * r01, f01.y * d0 * r01);
                    stg_cs_f2(sigbh + (size_t)(rg0+8)*TT + kv0 + cl,
                              f23.x * d3 * r23, f23.y * d2 * r23);
                    lsum0 += f01.x + f01.y;
                    lsum1 += f23.x + f23.y;
                    pf[j][jj*2]   = p01;
                    pf[j][jj*2+1] = p23;
                }
            }
            if (hn == 0) {                 // V(t) needed from here on
                if (t < 15) cpwait<1>(); else cpwait<0>();
                __syncthreads();
            }
            // ---- O += P(half) @ V(half-k) : m16 x n64 x k64 ----
            #pragma unroll
            for (int j = 0; j < 4; j++) {
                const uint32_t colb = (uint32_t)(hn*4 + j) * 32;
                #pragma unroll
                for (int bb = 0; bb < 4; bb++) {
                    uint32_t b0,b1,b2,b3;
                    ldsm4(b0,b1,b2,b3, sb + SVT_O + (bb*16)*272 + colb + boffV);
                    uint32_t bf0[2] = {b0,b1}, bf1[2] = {b2,b3};
                    mma16(o[bb*2],   pf[j], bf0);
                    mma16(o[bb*2+1], pf[j], bf1);
                }
            }
        }
    }

    // row sums: reduce across the 4 lanes sharing each row
    lsum0 += __shfl_xor_sync(0xffffffffu, lsum0, 1);
    lsum0 += __shfl_xor_sync(0xffffffffu, lsum0, 2);
    lsum1 += __shfl_xor_sync(0xffffffffu, lsum1, 1);
    lsum1 += __shfl_xor_sync(0xffffffffu, lsum1, 2);
    const float li0 = 1.0f / lsum0;
    const float li1 = 1.0f / lsum1;

    #pragma unroll
    for (int nt = 0; nt < 8; nt++) {
        const int cc = nt*8 + (lane & 3)*2;
        *(__half2*)(g_xh + ((size_t)bh*TT + rg0)*DKK + cc) =
            __floats2half2_rn(o[nt][0]*li0, o[nt][1]*li0);
        *(__half2*)(g_xh + ((size_t)bh*TT + rg0 + 8)*DKK + cc) =
            __floats2half2_rn(o[nt][2]*li1, o[nt][3]*li1);
    }
}

// -------------------------------------------------------------
extern "C" void kernel_launch(void* const* d_in, const int* in_sizes, int n_in,
                              void* d_out, int out_size)
{
    const float* query = (const float*)d_in[0];
    const float* key   = (const float*)d_in[1];
    const float* value = (const float*)d_in[2];
    const int*   mask  = (const int*)d_in[3];
    const float* Wq = (const float*)d_in[4];
    const float* bq = (const float*)d_in[5];
    const float* Wk = (const float*)d_in[6];
    const float* bk = (const float*)d_in[7];
    const float* Wv = (const float*)d_in[8];
    const float* bv = (const float*)d_in[9];
    const float* Wo = (const float*)d_in[10];
    const float* bo = (const float*)d_in[11];

    float* out0 = (float*)d_out;                 // (B,T,D)
    float* sig  = out0 + (size_t)BB * TT * DD;   // (B,H,T,T)

    static bool configured = false;
    if (!configured) {
        cudaFuncSetAttribute(attn_mma_kernel,
            cudaFuncAttributeMaxDynamicSharedMemorySize, ATT_SMEM);
        cudaFuncSetAttribute(qkv_mma_kernel,
            cudaFuncAttributeMaxDynamicSharedMemorySize, PJ_SMEM);
        cudaFuncSetAttribute(oproj_mma_kernel,
            cudaFuncAttributeMaxDynamicSharedMemorySize, PJ_SMEM);
        configured = true;
    }

    cvt_kernel<<<3328, 256>>>(query, key, value, Wq, Wk, Wv, Wo);
    qkv_mma_kernel<<<dim3(4, 64, 3), 256, PJ_SMEM>>>(bq, bk, bv);
    attn_mma_kernel<<<dim3(16, 32), 256, ATT_SMEM>>>(mask, sig);
    oproj_mma_kernel<<<dim3(4, 64), 256, PJ_SMEM>>>(bo, out0);
}

// round 17
// speedup vs baseline: 1.4618x; 1.0128x over previous
#include <cuda_runtime.h>
#include <cuda_fp16.h>
#include <cstdint>

#define BB 4
#define TT 2048
#define DD 512
#define HH 8
#define DKK 64

// fp16 scratch. q/k/x: [b,h,t,dk].  v: TRANSPOSED [b,h,dk,t].
__device__ __half g_qh[BB*HH*TT*DKK];
__device__ __half g_kh[BB*HH*TT*DKK];
__device__ __half g_vh[BB*HH*TT*DKK];
__device__ __half g_xh[BB*HH*TT*DKK];
// fp16 copies of inputs/weights
__device__ __half g_qi[BB*TT*DD];
__device__ __half g_ki[BB*TT*DD];
__device__ __half g_vi[BB*TT*DD];
__device__ __half g_wq[DD*DD];
__device__ __half g_wk[DD*DD];
__device__ __half g_wv[DD*DD];
__device__ __half g_wo[DD*DD];

__device__ __forceinline__ void mma16(float* d, const uint32_t* a, const uint32_t* b){
    asm volatile(
      "mma.sync.aligned.m16n8k16.row.col.f32.f16.f16.f32 "
      "{%0,%1,%2,%3}, {%4,%5,%6,%7}, {%8,%9}, {%0,%1,%2,%3};"
      : "+f"(d[0]),"+f"(d[1]),"+f"(d[2]),"+f"(d[3])
      : "r"(a[0]),"r"(a[1]),"r"(a[2]),"r"(a[3]), "r"(b[0]),"r"(b[1]));
}
__device__ __forceinline__ void ldsm4(uint32_t& r0, uint32_t& r1,
                                      uint32_t& r2, uint32_t& r3, uint32_t a){
    asm volatile("ldmatrix.sync.aligned.m8n8.x4.shared.b16 {%0,%1,%2,%3}, [%4];"
        : "=r"(r0),"=r"(r1),"=r"(r2),"=r"(r3) : "r"(a));
}
__device__ __forceinline__ uint2 f4h(float4 v){
    __half2 lo = __floats2half2_rn(v.x, v.y);
    __half2 hi = __floats2half2_rn(v.z, v.w);
    return make_uint2(*(uint32_t*)&lo, *(uint32_t*)&hi);
}
__device__ __forceinline__ uint32_t smem_u32(const void* p){
    uint32_t a;
    asm("{ .reg .u64 t; cvta.to.shared.u64 t, %1; cvt.u32.u64 %0, t; }"
        : "=r"(a) : "l"(p));
    return a;
}
__device__ __forceinline__ void cp16(uint32_t s, const void* g){
    asm volatile("cp.async.cg.shared.global [%0], [%1], 16;" :: "r"(s), "l"(g) : "memory");
}
__device__ __forceinline__ void cpcommit(){
    asm volatile("cp.async.commit_group;" ::: "memory");
}
template<int N> __device__ __forceinline__ void cpwait(){
    asm volatile("cp.async.wait_group %0;" :: "n"(N) : "memory");
}
__device__ __forceinline__ uint32_t ex2h2(uint32_t x){
    uint32_t r;
    asm("ex2.approx.f16x2 %0, %1;" : "=r"(r) : "r"(x));
    return r;
}
__device__ __forceinline__ float rcpf(float x){
    float r;
    asm("rcp.approx.ftz.f32 %0, %1;" : "=f"(r) : "f"(x));
    return r;
}
// streaming store: evict-first in L2 (sigmoid output is never re-read)
__device__ __forceinline__ void stg_cs_f2(float* p, float x, float y){
    asm volatile("st.global.cs.v2.f32 [%0], {%1,%2};"
        :: "l"(p), "f"(x), "f"(y) : "memory");
}

// =============================================================
// Convert fp32 inputs + weights to fp16 scratch
// =============================================================
#define IN4 1048576
#define W4  65536
__global__ __launch_bounds__(256) void cvt_kernel(
    const float* __restrict__ q, const float* __restrict__ k,
    const float* __restrict__ v,
    const float* __restrict__ Wq, const float* __restrict__ Wk,
    const float* __restrict__ Wv, const float* __restrict__ Wo)
{
    int i = blockIdx.x * 256 + threadIdx.x;
    const float* s; __half* d; int off;
    if (i < 3*IN4) {
        int w = i / IN4; off = i - w*IN4;
        s = w==0 ? q : (w==1 ? k : v);
        d = w==0 ? g_qi : (w==1 ? g_ki : g_vi);
    } else {
        int j = i - 3*IN4;
        int w = j / W4; off = j - w*W4;
        s = w==0 ? Wq : (w==1 ? Wk : (w==2 ? Wv : Wo));
        d = w==0 ? g_wq : (w==1 ? g_wk : (w==2 ? g_wv : g_wo));
    }
    float4 vv = __ldg((const float4*)s + off);
    *(uint2*)(d + (size_t)off*4) = f4h(vv);
}

// =============================================================
// QKV projection, fp16 + cp.async 3-stage + ldmatrix.
// smem: stage s @ s*36864 (A 18432 + B 18432), bias @110592
// =============================================================
#define PJ_SMEM 111104

__global__ __launch_bounds__(256, 2) void qkv_mma_kernel(
    const float* __restrict__ bq, const float* __restrict__ bk,
    const float* __restrict__ bv)
{
    extern __shared__ char smn[];
    const int which = blockIdx.z;
    const __half* A  = which == 0 ? g_qi : (which == 1 ? g_ki : g_vi);
    const __half* W  = which == 0 ? g_wq : (which == 1 ? g_wk : g_wv);
    const float* bias= which == 0 ? bq   : (which == 1 ? bk   : bv);
    __half* outp     = which == 0 ? g_qh : (which == 1 ? g_kh : g_vh);

    float* sBias = (float*)(smn + 110592);
    const uint32_t sb = smem_u32(smn);

    const int tid = threadIdx.x;
    const int lane = tid & 31, wid = tid >> 5;
    const int wm = wid & 1, wn = wid >> 1;
    const int m0 = blockIdx.y * 128, n0 = blockIdx.x * 128;

    if (tid < 32)
        *(float4*)&sBias[tid*4] = *(const float4*)(bias + n0 + tid*4);

    const int lrow = tid >> 3, lc8 = (tid & 7) * 8;
    const uint32_t aoff = (uint32_t)(((lane & 15) * 72 + ((lane >> 4) << 3)) * 2);
    const uint32_t boff = (uint32_t)((((lane & 7) + ((lane >> 4) << 3)) * 72 + (lane & 8)) * 2);

    auto issue = [&](int cc, int s){
        #pragma unroll
        for (int i = 0; i < 4; i++) {
            int row = lrow + i * 32;
            uint32_t so = sb + s*36864 + row*144 + lc8*2;
            cp16(so, A + (size_t)(m0+row)*512 + cc*64 + lc8);
            cp16(so + 18432, W + (size_t)(n0+row)*512 + cc*64 + lc8);
        }
        cpcommit();
    };

    issue(0, 0);
    issue(1, 1);
    issue(2, 2);

    float acc[4][4][4] = {};

    for (int c = 0; c < 8; c++) {
        if (c < 6) cpwait<2>();
        else if (c == 6) cpwait<1>();
        else cpwait<0>();
        __syncthreads();
        const uint32_t sbA = sb + (c % 3) * 36864;
        const uint32_t sbB = sbA + 18432;
        #pragma unroll
        for (int ks = 0; ks < 4; ks++) {
            uint32_t af[4][4], bf[4][2];
            #pragma unroll
            for (int mt = 0; mt < 4; mt++)
                ldsm4(af[mt][0], af[mt][1], af[mt][2], af[mt][3],
                      sbA + (wm*64 + mt*16)*144 + ks*32 + aoff);
            ldsm4(bf[0][0], bf[0][1], bf[1][0], bf[1][1],
                  sbB + (wn*32)*144 + ks*32 + boff);
            ldsm4(bf[2][0], bf[2][1], bf[3][0], bf[3][1],
                  sbB + (wn*32 + 16)*144 + ks*32 + boff);
            #pragma unroll
            for (int mt = 0; mt < 4; mt++)
                #pragma unroll
                for (int nt = 0; nt < 4; nt++)
                    mma16(acc[mt][nt], af[mt], bf[nt]);
        }
        __syncthreads();
        if (c + 3 < 8) issue(c + 3, c % 3);
    }

    #pragma unroll
    for (int mt = 0; mt < 4; mt++) {
        const int m = m0 + wm*64 + mt*16 + (lane>>2);
        const int b0_ = m >> 11, t0_ = m & 2047;
        const int b1_ = (m+8) >> 11, t1_ = (m+8) & 2047;
        #pragma unroll
        for (int nt = 0; nt < 4; nt++) {
            const int nl = wn*32 + nt*8 + (lane&3)*2;
            const int n = n0 + nl;
            const int h_ = n >> 6, dk_ = n & 63;
            float bx = sBias[nl], by = sBias[nl+1];
            float v0 = acc[mt][nt][0] + bx, v1 = acc[mt][nt][1] + by;
            float v2 = acc[mt][nt][2] + bx, v3 = acc[mt][nt][3] + by;
            if (which == 2) {
                __half* base = outp + ((size_t)(b0_*HH + h_)*DKK + dk_)*TT;
                base[t0_]       = __float2half_rn(v0);
                base[TT + t0_]  = __float2half_rn(v1);
                __half* base1 = outp + ((size_t)(b1_*HH + h_)*DKK + dk_)*TT;
                base1[t1_]      = __float2half_rn(v2);
                base1[TT + t1_] = __float2half_rn(v3);
            } else {
                *(__half2*)(outp + (((size_t)b0_*HH + h_)*TT + t0_)*DKK + dk_) =
                    __floats2half2_rn(v0, v1);
                *(__half2*)(outp + (((size_t)b1_*HH + h_)*TT + t1_)*DKK + dk_) =
                    __floats2half2_rn(v2, v3);
            }
        }
    }
}

// =============================================================
// Output projection: A = g_xh (head-split fp16), B = g_wo fp16
// =============================================================
__global__ __launch_bounds__(256, 2) void oproj_mma_kernel(
    const float* __restrict__ bo, float* __restrict__ outp)
{
    extern __shared__ char smn[];
    float* sBias = (float*)(smn + 110592);
    const uint32_t sb = smem_u32(smn);

    const int tid = threadIdx.x;
    const int lane = tid & 31, wid = tid >> 5;
    const int wm = wid & 1, wn = wid >> 1;
    const int m0 = blockIdx.y * 128, n0 = blockIdx.x * 128;

    if (tid < 32)
        *(float4*)&sBias[tid*4] = *(const float4*)(bo + n0 + tid*4);

    const int lrow = tid >> 3, lc8 = (tid & 7) * 8;
    const uint32_t aoff = (uint32_t)(((lane & 15) * 72 + ((lane >> 4) << 3)) * 2);
    const uint32_t boff = (uint32_t)((((lane & 7) + ((lane >> 4) << 3)) * 72 + (lane & 8)) * 2);

    auto issue = [&](int cc, int s){
        #pragma unroll
        for (int i = 0; i < 4; i++) {
            int row = lrow + i * 32;
            const int m = m0 + row;
            const int b_ = m >> 11, t_ = m & 2047;
            uint32_t so = sb + s*36864 + row*144 + lc8*2;
            cp16(so, g_xh + (((size_t)b_*HH + cc)*TT + t_)*DKK + lc8);
            cp16(so + 18432, g_wo + (size_t)(n0+row)*512 + cc*64 + lc8);
        }
        cpcommit();
    };

    issue(0, 0);
    issue(1, 1);
    issue(2, 2);

    float acc[4][4][4] = {};

    for (int c = 0; c < 8; c++) {
        if (c < 6) cpwait<2>();
        else if (c == 6) cpwait<1>();
        else cpwait<0>();
        __syncthreads();
        const uint32_t sbA = sb + (c % 3) * 36864;
        const uint32_t sbB = sbA + 18432;
        #pragma unroll
        for (int ks = 0; ks < 4; ks++) {
            uint32_t af[4][4], bf[4][2];
            #pragma unroll
            for (int mt = 0; mt < 4; mt++)
                ldsm4(af[mt][0], af[mt][1], af[mt][2], af[mt][3],
                      sbA + (wm*64 + mt*16)*144 + ks*32 + aoff);
            ldsm4(bf[0][0], bf[0][1], bf[1][0], bf[1][1],
                  sbB + (wn*32)*144 + ks*32 + boff);
            ldsm4(bf[2][0], bf[2][1], bf[3][0], bf[3][1],
                  sbB + (wn*32 + 16)*144 + ks*32 + boff);
            #pragma unroll
            for (int mt = 0; mt < 4; mt++)
                #pragma unroll
                for (int nt = 0; nt < 4; nt++)
                    mma16(acc[mt][nt], af[mt], bf[nt]);
        }
        __syncthreads();
        if (c + 3 < 8) issue(c + 3, c % 3);
    }

    #pragma unroll
    for (int mt = 0; mt < 4; mt++) {
        const int m = m0 + wm*64 + mt*16 + (lane>>2);
        #pragma unroll
        for (int nt = 0; nt < 4; nt++) {
            const int nl = wn*32 + nt*8 + (lane&3)*2;
            float bx = sBias[nl], by = sBias[nl+1];
            *(float2*)(outp + (size_t)m*512 + n0 + nl) =
                make_float2(acc[mt][nt][0] + bx, acc[mt][nt][1] + by);
            *(float2*)(outp + (size_t)(m+8)*512 + n0 + nl) =
                make_float2(acc[mt][nt][2] + bx, acc[mt][nt][3] + by);
        }
    }
}

// =============================================================
// Fused attention, FA2-style (half-split body), 2 CTAs/SM,
// .cs sigmoid stores, 4-way batched rcp.
// smem: sQ@0 (18432), sK ring @18432 (2x18432), sVt@55296 (17408)
// =============================================================
#define SQ_O 0
#define SK_O 18432
#define SVT_O 55296
#define ATT_SMEM 72704

__global__ __launch_bounds__(256, 2) void attn_mma_kernel(
    const int* __restrict__ mask, float* __restrict__ sig)
{
    extern __shared__ char smn[];
    const uint32_t sb = smem_u32(smn);

    const int tid = threadIdx.x;
    const int lane = tid & 31, wid = tid >> 5;
    const int wrow = wid * 16;                 // warp's q rows [wrow, wrow+16)
    const int bh = blockIdx.y;
    const int b_ = bh >> 3;
    const int q0 = blockIdx.x * 128;

    const __half* Qg = g_qh + (size_t)bh * TT * DKK;
    const __half* Kg = g_kh + (size_t)bh * TT * DKK;
    const __half* Vg = g_vh + (size_t)bh * DKK * TT;   // [dk][t]
    float* sigbh = sig + (size_t)bh * TT * TT;
    const int* maskb = mask + b_ * TT;

    const int krow = tid >> 3, kc8 = (tid & 7) * 8;
    const int vdk = tid >> 4, vc8 = (tid & 15) * 8;

    const uint32_t aoff  = (uint32_t)(((lane & 15) * 72 + ((lane >> 4) << 3)) * 2);
    const uint32_t boff  = (uint32_t)((((lane & 7) + ((lane >> 4) << 3)) * 72 + (lane & 8)) * 2);
    const uint32_t boffV = (uint32_t)((((lane & 7) + ((lane >> 4) << 3)) * 136 + (lane & 8)) * 2);

    // group 0: Q ; group 1: K(0)
    #pragma unroll
    for (int i = 0; i < 4; i++) {
        int row = krow + i * 32;
        cp16(sb + SQ_O + row*144 + kc8*2, Qg + (size_t)(q0+row)*DKK + kc8);
    }
    cpcommit();
    #pragma unroll
    for (int i = 0; i < 4; i++) {
        int row = krow + i * 32;
        cp16(sb + SK_O + row*144 + kc8*2, Kg + (size_t)row*DKK + kc8);
    }
    cpcommit();

    float o[8][4] = {};
    float lsum0 = 0.0f, lsum1 = 0.0f;
    uint32_t qf[4][4];
    const float SC = 0.180336880f;   // 0.125 * log2(e)
    const int rg0 = q0 + wrow + (lane >> 2);

    for (int t = 0; t < 16; t++) {
        const int kv0 = t * 128;
        __syncthreads();   // PV(t-1) done reading sVt

        // group: V(t)
        #pragma unroll
        for (int i = 0; i < 4; i++) {
            int dk = vdk + i * 16;
            cp16(sb + SVT_O + dk*272 + vc8*2, Vg + (size_t)dk*TT + kv0 + vc8);
        }
        cpcommit();
        // group: K(t+1)
        if (t < 15) {
            const uint32_t kb = sb + SK_O + ((t+1) & 1) * 18432;
            #pragma unroll
            for (int i = 0; i < 4; i++) {
                int row = krow + i * 32;
                cp16(kb + row*144 + kc8*2, Kg + (size_t)(kv0+128+row)*DKK + kc8);
            }
            cpcommit();
            cpwait<2>();   // K(t) (and Q at t=0) arrived
        } else {
            cpwait<1>();
        }
        __syncthreads();

        if (t == 0) {      // hoist Q fragments into registers, once
            #pragma unroll
            for (int ks = 0; ks < 4; ks++)
                ldsm4(qf[ks][0], qf[ks][1], qf[ks][2], qf[ks][3],
                      sb + SQ_O + wrow*144 + ks*32 + aoff);
        }

        const uint32_t sbK = sb + SK_O + (t & 1) * 18432;

        #pragma unroll
        for (int hn = 0; hn < 2; hn++) {
            // ---- S(half) = Q @ K^T : m16 x n64 x k64 ----
            float s[8][4] = {};
            #pragma unroll
            for (int ks = 0; ks < 4; ks++) {
                #pragma unroll
                for (int np = 0; np < 4; np++) {
                    uint32_t b0,b1,b2,b3;
                    ldsm4(b0,b1,b2,b3, sbK + (hn*64 + np*16)*144 + ks*32 + boff);
                    uint32_t bf0[2] = {b0,b1}, bf1[2] = {b2,b3};
                    mma16(s[np*2],   qf[ks], bf0);
                    mma16(s[np*2+1], qf[ks], bf1);
                }
            }
            // ---- epilogue: sigmoid -> gmem (.cs), P -> regs ----
            uint32_t pf[4][4];
            #pragma unroll
            for (int j = 0; j < 4; j++) {
                #pragma unroll
                for (int jj = 0; jj < 2; jj++) {
                    const int nt = j*2 + jj;
                    const int cl = hn*64 + nt*8 + (lane & 3)*2;
                    int2 mm = __ldg((const int2*)(maskb + kv0 + cl));
                    const float m0_ = mm.x ? 0.0f : -1e9f;
                    const float m1_ = mm.y ? 0.0f : -1e9f;
                    float s0 = fmaf(s[nt][0], SC, m0_);
                    float s1 = fmaf(s[nt][1], SC, m1_);
                    float s2 = fmaf(s[nt][2], SC, m0_);
                    float s3 = fmaf(s[nt][3], SC, m1_);
                    __half2 h01 = __floats2half2_rn(s0, s1);
                    __half2 h23 = __floats2half2_rn(s2, s3);
                    uint32_t p01 = ex2h2(*(uint32_t*)&h01);
                    uint32_t p23 = ex2h2(*(uint32_t*)&h23);
                    float2 f01 = __half22float2(*(__half2*)&p01);
                    float2 f23 = __half22float2(*(__half2*)&p23);
                    // 4-way batched reciprocal: one MUFU.RCP for 4 sigmoids
                    float d0 = 1.0f + f01.x, d1 = 1.0f + f01.y;
                    float d2 = 1.0f + f23.x, d3 = 1.0f + f23.y;
                    float d01 = d0 * d1, d23 = d2 * d3;
                    float r = rcpf(d01 * d23);
                    float r01 = r * d23, r23 = r * d01;
                    stg_cs_f2(sigbh + (size_t)rg0*TT + kv0 + cl,
                              f01.x * d1 * r01, f01.y * d0 * r01);
                    stg_cs_f2(sigbh + (size_t)(rg0+8)*TT + kv0 + cl,
                              f23.x * d3 * r23, f23.y * d2 * r23);
                    lsum0 += f01.x + f01.y;
                    lsum1 += f23.x + f23.y;
                    pf[j][jj*2]   = p01;
                    pf[j][jj*2+1] = p23;
                }
            }
            if (hn == 0) {                 // V(t) needed from here on
                if (t < 15) cpwait<1>(); else cpwait<0>();
                __syncthreads();
            }
            // ---- O += P(half) @ V(half-k) : m16 x n64 x k64 ----
            #pragma unroll
            for (int j = 0; j < 4; j++) {
                const uint32_t colb = (uint32_t)(hn*4 + j) * 32;
                #pragma unroll
                for (int bb = 0; bb < 4; bb++) {
                    uint32_t b0,b1,b2,b3;
                    ldsm4(b0,b1,b2,b3, sb + SVT_O + (bb*16)*272 + colb + boffV);
                    uint32_t bf0[2] = {b0,b1}, bf1[2] = {b2,b3};
                    mma16(o[bb*2],   pf[j], bf0);
                    mma16(o[bb*2+1], pf[j], bf1);
                }
            }
        }
    }

    // row sums: reduce across the 4 lanes sharing each row
    lsum0 += __shfl_xor_sync(0xffffffffu, lsum0, 1);
    lsum0 += __shfl_xor_sync(0xffffffffu, lsum0, 2);
    lsum1 += __shfl_xor_sync(0xffffffffu, lsum1, 1);
    lsum1 += __shfl_xor_sync(0xffffffffu, lsum1, 2);
    const float li0 = 1.0f / lsum0;
    const float li1 = 1.0f / lsum1;

    #pragma unroll
    for (int nt = 0; nt < 8; nt++) {
        const int cc = nt*8 + (lane & 3)*2;
        *(__half2*)(g_xh + ((size_t)bh*TT + rg0)*DKK + cc) =
            __floats2half2_rn(o[nt][0]*li0, o[nt][1]*li0);
        *(__half2*)(g_xh + ((size_t)bh*TT + rg0 + 8)*DKK + cc) =
            __floats2half2_rn(o[nt][2]*li1, o[nt][3]*li1);
    }
}

// -------------------------------------------------------------
extern "C" void kernel_launch(void* const* d_in, const int* in_sizes, int n_in,
                              void* d_out, int out_size)
{
    const float* query = (const float*)d_in[0];
    const float* key   = (const float*)d_in[1];
    const float* value = (const float*)d_in[2];
    const int*   mask  = (const int*)d_in[3];
    const float* Wq = (const float*)d_in[4];
    const float* bq = (const float*)d_in[5];
    const float* Wk = (const float*)d_in[6];
    const float* bk = (const float*)d_in[7];
    const float* Wv = (const float*)d_in[8];
    const float* bv = (const float*)d_in[9];
    const float* Wo = (const float*)d_in[10];
    const float* bo = (const float*)d_in[11];

    float* out0 = (float*)d_out;                 // (B,T,D)
    float* sig  = out0 + (size_t)BB * TT * DD;   // (B,H,T,T)

    static bool configured = false;
    if (!configured) {
        cudaFuncSetAttribute(attn_mma_kernel,
            cudaFuncAttributeMaxDynamicSharedMemorySize, ATT_SMEM);
        cudaFuncSetAttribute(qkv_mma_kernel,
            cudaFuncAttributeMaxDynamicSharedMemorySize, PJ_SMEM);
        cudaFuncSetAttribute(oproj_mma_kernel,
            cudaFuncAttributeMaxDynamicSharedMemorySize, PJ_SMEM);
        configured = true;
    }

    cvt_kernel<<<13312, 256>>>(query, key, value, Wq, Wk, Wv, Wo);
    qkv_mma_kernel<<<dim3(4, 64, 3), 256, PJ_SMEM>>>(bq, bk, bv);
    attn_mma_kernel<<<dim3(16, 32), 256, ATT_SMEM>>>(mask, sig);
    oproj_mma_kernel<<<dim3(4, 64), 256, PJ_SMEM>>>(bo, out0);
}